// round 1
// baseline (speedup 1.0000x reference)
#include <cuda_runtime.h>
#include <cstdint>

#define B_ 64
#define T_ 1024
#define I_ 256
#define H_ 512
#define O_ 256
#define G_ 1536   // 3*H

// -------- scratch (device globals: allocation-free) --------
__device__ float g_xt[(size_t)T_ * I_ * B_];      // [t][k][b]   64 MB
__device__ float g_gates[(size_t)T_ * G_ * B_];   // [t][g][b]  402 MB
__device__ float g_out0[(size_t)T_ * H_ * B_];    // [t][h][b]  134 MB
__device__ float g_out1[(size_t)T_ * H_ * B_];    // [t][h][b]  134 MB
__device__ unsigned g_barc;                        // grid barrier counter
__device__ unsigned g_gen;                         // grid barrier generation

// =========================================================================
// Transpose x[b][t][k] -> xt[t][k][b]
// =========================================================================
__global__ __launch_bounds__(256) void k_transpose(const float* __restrict__ x) {
    __shared__ float sm[64][65];
    int t  = blockIdx.x;
    int k0 = blockIdx.y * 64;
    int c = threadIdx.x & 63;   // lane dim
    int r = threadIdx.x >> 6;   // 0..3
#pragma unroll
    for (int i = 0; i < 16; i++) {
        int b = r + i * 4;
        sm[b][c] = x[((size_t)b * T_ + t) * I_ + k0 + c];   // coalesced over k
    }
    __syncthreads();
#pragma unroll
    for (int i = 0; i < 16; i++) {
        int kk = r + i * 4;
        g_xt[((size_t)t * I_ + k0 + kk) * B_ + c] = sm[c][kk];  // coalesced over b
    }
}

// =========================================================================
// Batched GEMM: C_t[M][64] = A[M][K] @ Bt[t][K][64] + bias[M]
//   mode 0: C[t][m][b]  (b-contiguous, for gates buffers)
//   mode 1: C[(b*T + t)*M + m]  (final FC output layout)
// Tile: 128(M) x 64(N=B) x 16(K). 256 threads, each 8x4 micro-tile.
// =========================================================================
__global__ __launch_bounds__(256) void k_gemm(
    const float* __restrict__ A, const float* __restrict__ Bt,
    const float* __restrict__ bias, float* __restrict__ C,
    int M, int K, int mode)
{
    __shared__ float As[16][132];   // [k][m], padded
    __shared__ float Bs[16][64];    // [k][b]

    int t   = blockIdx.y;
    int m0  = blockIdx.x * 128;
    int tid = threadIdx.x;
    int tx  = tid & 15;    // -> b0 = tx*4
    int ty  = tid >> 4;    // -> m-sub = ty*8

    float acc[8][4];
#pragma unroll
    for (int i = 0; i < 8; i++)
#pragma unroll
        for (int j = 0; j < 4; j++) acc[i][j] = 0.f;

    const float* Bbase = Bt + (size_t)t * K * B_;

    for (int k0 = 0; k0 < K; k0 += 16) {
        // load A tile (128 x 16), transposed into As[k][m]
#pragma unroll
        for (int l = 0; l < 2; l++) {
            int f = tid + l * 256;       // 0..511
            int m = f >> 2;              // 0..127
            int q = f & 3;               // which k-quad
            float4 v = *(const float4*)(A + (size_t)(m0 + m) * K + k0 + q * 4);
            As[q * 4 + 0][m] = v.x;
            As[q * 4 + 1][m] = v.y;
            As[q * 4 + 2][m] = v.z;
            As[q * 4 + 3][m] = v.w;
        }
        // load B tile (16 x 64), already [k][b]
        {
            int k  = tid >> 4;
            int b4 = (tid & 15) * 4;
            *(float4*)&Bs[k][b4] = *(const float4*)(Bbase + (size_t)(k0 + k) * B_ + b4);
        }
        __syncthreads();
#pragma unroll
        for (int k = 0; k < 16; k++) {
            float a[8], bv[4];
            *(float4*)&a[0] = *(float4*)&As[k][ty * 8];
            *(float4*)&a[4] = *(float4*)&As[k][ty * 8 + 4];
            *(float4*)&bv[0] = *(float4*)&Bs[k][tx * 4];
#pragma unroll
            for (int i = 0; i < 8; i++)
#pragma unroll
                for (int j = 0; j < 4; j++)
                    acc[i][j] += a[i] * bv[j];
        }
        __syncthreads();
    }

    if (mode == 0) {
#pragma unroll
        for (int i = 0; i < 8; i++) {
            int m = m0 + ty * 8 + i;
            float bb = bias[m];
            float4 v = make_float4(acc[i][0] + bb, acc[i][1] + bb,
                                   acc[i][2] + bb, acc[i][3] + bb);
            *(float4*)(C + ((size_t)t * M + m) * B_ + tx * 4) = v;
        }
    } else {
#pragma unroll
        for (int i = 0; i < 8; i++) {
            int m = m0 + ty * 8 + i;
            float bb = bias[m];
#pragma unroll
            for (int j = 0; j < 4; j++) {
                int b = tx * 4 + j;
                C[((size_t)b * T_ + t) * M + m] = acc[i][j] + bb;
            }
        }
    }
}

// =========================================================================
// Persistent GRU layer. 128 CTAs x 256 threads, all co-resident.
// CTA c owns h-cols [4c, 4c+4). SMEM: W slice [12][512] + full h [512][64].
// Per step: hg dot-products from SMEM, gate math, write h_new to out[t],
// grid barrier, reload full h into SMEM.
// =========================================================================
__device__ __forceinline__ void grid_sync() {
    __syncthreads();
    if (threadIdx.x == 0) {
        __threadfence();
        volatile unsigned* genp = &g_gen;
        unsigned g = *genp;
        if (atomicAdd(&g_barc, 1) == gridDim.x - 1) {
            atomicExch(&g_barc, 0);
            __threadfence();
            *genp = g + 1;
        } else {
            while (*genp == g) { }
        }
        __threadfence();
    }
    __syncthreads();
}

#define GRU_SMEM_BYTES ((12 * 512 + 512 * 64) * 4)

__global__ __launch_bounds__(256) void k_gru(
    const float* __restrict__ gates,   // [t][g][b], includes b_ih
    const float* __restrict__ Whh,     // [3H][H]
    const float* __restrict__ bhh,     // [3H]
    float* __restrict__ out)           // [t][h][b]
{
    extern __shared__ float smem[];
    float* Ws = smem;              // [ (jj*3+g) ][512]
    float* hs = smem + 12 * 512;   // [k][b]

    int tid = threadIdx.x;
    int b  = tid & 63;
    int jj = tid >> 6;             // 0..3
    int j0 = blockIdx.x * 4;
    int j  = j0 + jj;

    // load W slice: rows {j0+w, H+j0+w, 2H+j0+w} for w=0..3
    for (int idx = tid; idx < 12 * 512; idx += 256) {
        int lr = idx >> 9;          // 0..11 = w*3+g
        int k  = idx & 511;
        int g  = lr % 3;
        int w  = lr / 3;
        Ws[idx] = Whh[((size_t)(g * H_ + j0 + w)) * H_ + k];
    }
    for (int idx = tid; idx < H_ * B_; idx += 256) hs[idx] = 0.f;  // h0 = 0

    float bhr = bhh[j];
    float bhz = bhh[H_ + j];
    float bhn = bhh[2 * H_ + j];
    const float* Wr = Ws + (jj * 3 + 0) * 512;
    const float* Wz = Ws + (jj * 3 + 1) * 512;
    const float* Wn = Ws + (jj * 3 + 2) * 512;
    __syncthreads();

    for (int t = 0; t < T_; t++) {
        float ar = 0.f, az = 0.f, an = 0.f;
#pragma unroll 4
        for (int k = 0; k < H_; k += 4) {
            float4 wr = *(const float4*)(Wr + k);
            float4 wz = *(const float4*)(Wz + k);
            float4 wn = *(const float4*)(Wn + k);
            float h0v = hs[(k + 0) * B_ + b];
            float h1v = hs[(k + 1) * B_ + b];
            float h2v = hs[(k + 2) * B_ + b];
            float h3v = hs[(k + 3) * B_ + b];
            ar += wr.x * h0v; az += wz.x * h0v; an += wn.x * h0v;
            ar += wr.y * h1v; az += wz.y * h1v; an += wn.y * h1v;
            ar += wr.z * h2v; az += wz.z * h2v; an += wn.z * h2v;
            ar += wr.w * h3v; az += wz.w * h3v; an += wn.w * h3v;
        }
        const float* gt = gates + (size_t)t * G_ * B_;
        float xr = __ldcg(gt + (size_t)(0 * H_ + j) * B_ + b);
        float xz = __ldcg(gt + (size_t)(1 * H_ + j) * B_ + b);
        float xn = __ldcg(gt + (size_t)(2 * H_ + j) * B_ + b);

        float r = 1.f / (1.f + expf(-(xr + ar + bhr)));
        float z = 1.f / (1.f + expf(-(xz + az + bhz)));
        float n = tanhf(xn + r * (an + bhn));
        float hold = hs[(size_t)j * B_ + b];
        float hnew = (1.f - z) * n + z * hold;

        out[((size_t)t * H_ + j) * B_ + b] = hnew;

        grid_sync();   // h_t globally visible

        // reload full h into SMEM (bypass L1: written by other SMs)
        const float4* src = (const float4*)(out + (size_t)t * H_ * B_);
        float4* dst = (float4*)hs;
        for (int idx = tid; idx < (H_ * B_) / 4; idx += 256)
            dst[idx] = __ldcg(src + idx);
        __syncthreads();
    }
}

// =========================================================================
// hidden[l][b][h] = out_l[t=T-1][h][b]
// =========================================================================
__global__ __launch_bounds__(256) void k_hidden(float* __restrict__ dst) {
    int idx = blockIdx.x * 256 + threadIdx.x;   // 0..65535
    int l  = idx >> 15;
    int rem = idx & 32767;
    int bb = rem >> 9;
    int h  = rem & 511;
    const float* src = l ? g_out1 : g_out0;
    dst[idx] = src[((size_t)(T_ - 1) * H_ + h) * B_ + bb];
}

// =========================================================================
extern "C" void kernel_launch(void* const* d_in, const int* in_sizes, int n_in,
                              void* d_out, int out_size) {
    const float* x    = (const float*)d_in[0];
    const float* Wih0 = (const float*)d_in[1];
    const float* Whh0 = (const float*)d_in[2];
    const float* bih0 = (const float*)d_in[3];
    const float* bhh0 = (const float*)d_in[4];
    const float* Wih1 = (const float*)d_in[5];
    const float* Whh1 = (const float*)d_in[6];
    const float* bih1 = (const float*)d_in[7];
    const float* bhh1 = (const float*)d_in[8];
    const float* fcw  = (const float*)d_in[9];
    const float* fcb  = (const float*)d_in[10];
    float* out = (float*)d_out;

    (void)in_sizes; (void)n_in; (void)out_size;

    cudaFuncSetAttribute(k_gru, cudaFuncAttributeMaxDynamicSharedMemorySize,
                         GRU_SMEM_BYTES);

    float *p_xt, *p_gates, *p_out0, *p_out1;
    cudaGetSymbolAddress((void**)&p_xt,    g_xt);
    cudaGetSymbolAddress((void**)&p_gates, g_gates);
    cudaGetSymbolAddress((void**)&p_out0,  g_out0);
    cudaGetSymbolAddress((void**)&p_out1,  g_out1);

    // 1) x -> xt[t][k][b]
    k_transpose<<<dim3(1024, 4), 256>>>(x);
    // 2) gates0 = W_ih0 @ x_t + b_ih0   -> [t][g][b]
    k_gemm<<<dim3(G_ / 128, T_), 256>>>(Wih0, p_xt, bih0, p_gates, G_, I_, 0);
    // 3) layer-0 recurrence (persistent)
    k_gru<<<128, 256, GRU_SMEM_BYTES>>>(p_gates, Whh0, bhh0, p_out0);
    // 4) gates1 = W_ih1 @ out0_t + b_ih1
    k_gemm<<<dim3(G_ / 128, T_), 256>>>(Wih1, p_out0, bih1, p_gates, G_, H_, 0);
    // 5) layer-1 recurrence
    k_gru<<<128, 256, GRU_SMEM_BYTES>>>(p_gates, Whh1, bhh1, p_out1);
    // 6) FC: out[b*T+t][o] = fc_w @ out1_t + fc_b
    k_gemm<<<dim3(O_ / 128, T_), 256>>>(fcw, p_out1, fcb, out, O_, H_, 1);
    // 7) hidden states
    k_hidden<<<256, 256>>>(out + (size_t)B_ * T_ * O_);
}

// round 2
// speedup vs baseline: 1.1652x; 1.1652x over previous
#include <cuda_runtime.h>
#include <cstdint>

#define B_ 64
#define T_ 1024
#define I_ 256
#define H_ 512
#define O_ 256
#define G_ 1536   // 3*H

// -------- scratch (device globals: allocation-free) --------
__device__ float g_xt[(size_t)T_ * I_ * B_];      // [t][k][b]
__device__ float g_gates[(size_t)T_ * G_ * B_];   // [t][g][b]
__device__ float g_out0[(size_t)T_ * H_ * B_];    // [t][h][b]
__device__ float g_out1[(size_t)T_ * H_ * B_];    // [t][h][b]
__device__ volatile unsigned g_cnt[4 * 32];        // per-group barrier counters (padded)
__device__ volatile unsigned g_gen2[4 * 32];       // per-group generations (padded)

// =========================================================================
// Transpose x[b][t][k] -> xt[t][k][b]
// =========================================================================
__global__ __launch_bounds__(256) void k_transpose(const float* __restrict__ x) {
    __shared__ float sm[64][65];
    int t  = blockIdx.x;
    int k0 = blockIdx.y * 64;
    int c = threadIdx.x & 63;
    int r = threadIdx.x >> 6;
#pragma unroll
    for (int i = 0; i < 16; i++) {
        int b = r + i * 4;
        sm[b][c] = x[((size_t)b * T_ + t) * I_ + k0 + c];
    }
    __syncthreads();
#pragma unroll
    for (int i = 0; i < 16; i++) {
        int kk = r + i * 4;
        g_xt[((size_t)t * I_ + k0 + kk) * B_ + c] = sm[c][kk];
    }
}

// =========================================================================
// Batched GEMM over pairs of timesteps:
//   C_t[M][64] = A[M][K] @ Bt[t][K][64] + bias[M], N-tile = 128 = 2 timesteps
//   mode 0: C[t][m][b]   mode 1: C[(b*T + t)*M + m]
// Tile: 128(M) x 128(N) x 16(K). 256 threads, 8x8 micro-tile.
// =========================================================================
__global__ __launch_bounds__(256) void k_gemm2(
    const float* __restrict__ A, const float* __restrict__ Bt,
    const float* __restrict__ bias, float* __restrict__ C,
    int M, int K, int mode)
{
    __shared__ float As[16][132];   // [k][m], padded
    __shared__ float Bs[16][128];   // [k][n]  n = t2*64 + b

    int t0  = blockIdx.y * 2;
    int m0  = blockIdx.x * 128;
    int tid = threadIdx.x;
    int tx  = tid & 15;    // n-sub = tx*8
    int ty  = tid >> 4;    // m-sub = ty*8

    float acc[8][8];
#pragma unroll
    for (int i = 0; i < 8; i++)
#pragma unroll
        for (int j = 0; j < 8; j++) acc[i][j] = 0.f;

    const float* Bbase = Bt + (size_t)t0 * K * B_;

    for (int k0 = 0; k0 < K; k0 += 16) {
        // A tile 128x16, transposed into As[k][m]
#pragma unroll
        for (int l = 0; l < 2; l++) {
            int f = tid + l * 256;
            int m = f >> 2;
            int q = f & 3;
            float4 v = *(const float4*)(A + (size_t)(m0 + m) * K + k0 + q * 4);
            As[q * 4 + 0][m] = v.x;
            As[q * 4 + 1][m] = v.y;
            As[q * 4 + 2][m] = v.z;
            As[q * 4 + 3][m] = v.w;
        }
        // B tile 16x128 (two timesteps)
#pragma unroll
        for (int l = 0; l < 2; l++) {
            int f  = tid + l * 256;      // 0..511
            int n4 = f & 31;             // float4 index in n
            int k  = f >> 5;             // 0..15
            int t2 = n4 >> 4;            // which timestep
            float4 v = *(const float4*)(Bbase + ((size_t)t2 * K + k0 + k) * B_ + (n4 & 15) * 4);
            *(float4*)&Bs[k][n4 * 4] = v;
        }
        __syncthreads();
#pragma unroll
        for (int k = 0; k < 16; k++) {
            float a[8], bv[8];
            *(float4*)&a[0]  = *(float4*)&As[k][ty * 8];
            *(float4*)&a[4]  = *(float4*)&As[k][ty * 8 + 4];
            *(float4*)&bv[0] = *(float4*)&Bs[k][tx * 8];
            *(float4*)&bv[4] = *(float4*)&Bs[k][tx * 8 + 4];
#pragma unroll
            for (int i = 0; i < 8; i++)
#pragma unroll
                for (int j = 0; j < 8; j++)
                    acc[i][j] += a[i] * bv[j];
        }
        __syncthreads();
    }

#pragma unroll
    for (int i = 0; i < 8; i++) {
        int m = m0 + ty * 8 + i;
        float bb = bias[m];
#pragma unroll
        for (int j = 0; j < 8; j++) {
            int n = tx * 8 + j;
            int t = t0 + (n >> 6);
            int b = n & 63;
            float v = acc[i][j] + bb;
            if (mode == 0)
                C[((size_t)t * M + m) * B_ + b] = v;
            else
                C[((size_t)b * T_ + t) * M + m] = v;
        }
    }
}

// =========================================================================
// Persistent GRU layer, batch-partitioned groups.
// 128 CTAs = 4 batch-groups (16 b each) x 32 j-subs (16 j each).
// SMEM: Ws slice 48x520 fp32 (~97.5KB) + h slice [16 b][516] (~32KB).
// Per step: dot from SMEM, gate math, STG h_new, per-group barrier,
// reload group's h slice (32KB) from L2, repeat.
// =========================================================================
#define WS_STRIDE 520
#define HS_STRIDE 516
#define GRU_SMEM_FLOATS (48 * WS_STRIDE + 16 * HS_STRIDE)
#define GRU_SMEM_BYTES (GRU_SMEM_FLOATS * 4)

__global__ __launch_bounds__(256) void k_gru2(
    const float* __restrict__ gates,   // [t][g][b], includes b_ih
    const float* __restrict__ Whh,     // [3H][H]
    const float* __restrict__ bhh,     // [3H]
    float* __restrict__ out)           // [t][h][b]
{
    extern __shared__ float smem[];
    float* Ws = smem;                      // 48 rows (jj*3+g) x WS_STRIDE
    float* hs = smem + 48 * WS_STRIDE;     // [16 b][HS_STRIDE]

    int tid   = threadIdx.x;
    int group = blockIdx.x >> 5;    // 0..3 (batch group)
    int sub   = blockIdx.x & 31;    // 0..31 (j partition)
    int jj    = tid >> 4;           // 0..15
    int bl    = tid & 15;           // 0..15
    int j0    = sub * 16;
    int bg0   = group * 16;
    int j     = j0 + jj;
    int b     = bg0 + bl;
    int gidx  = group * 32;

    // Load Whh slice: rows (jj*3+g) <- Whh[g*H + j0 + jj]
    for (int idx = tid; idx < 48 * 512; idx += 256) {
        int r = idx >> 9;           // 0..47
        int k = idx & 511;
        int gg = r % 3;
        int ww = r / 3;
        Ws[r * WS_STRIDE + k] = Whh[((size_t)(gg * H_ + j0 + ww)) * H_ + k];
    }
    // h0 = 0
    for (int idx = tid; idx < 16 * HS_STRIDE; idx += 256) hs[idx] = 0.f;

    float bhr = bhh[j];
    float bhz = bhh[H_ + j];
    float bhn = bhh[2 * H_ + j];

    const float4* Wr = (const float4*)(Ws + (jj * 3 + 0) * WS_STRIDE);
    const float4* Wz = (const float4*)(Ws + (jj * 3 + 1) * WS_STRIDE);
    const float4* Wn = (const float4*)(Ws + (jj * 3 + 2) * WS_STRIDE);
    const float4* hp = (const float4*)(hs + bl * HS_STRIDE);

    const float* gp = gates + (size_t)j * B_ + b;   // gate 0, t=0
    const size_t tstride = (size_t)G_ * B_;
    const size_t goff    = (size_t)H_ * B_;

    // prefetch gates for t=0
    float xr = __ldcs(gp);
    float xz = __ldcs(gp + goff);
    float xn = __ldcs(gp + 2 * goff);

    __syncthreads();

    for (int t = 0; t < T_; t++) {
        float ar = 0.f, az = 0.f, an = 0.f;
#pragma unroll 8
        for (int k4 = 0; k4 < 128; k4++) {
            float4 h4 = hp[k4];
            float4 wr = Wr[k4];
            float4 wz = Wz[k4];
            float4 wn = Wn[k4];
            ar += wr.x * h4.x; az += wz.x * h4.x; an += wn.x * h4.x;
            ar += wr.y * h4.y; az += wz.y * h4.y; an += wn.y * h4.y;
            ar += wr.z * h4.z; az += wz.z * h4.z; an += wn.z * h4.z;
            ar += wr.w * h4.w; az += wz.w * h4.w; an += wn.w * h4.w;
        }

        float r = 1.f / (1.f + expf(-(xr + ar + bhr)));
        float z = 1.f / (1.f + expf(-(xz + az + bhz)));
        float n = tanhf(xn + r * (an + bhn));
        float hold = hs[bl * HS_STRIDE + j];   // only valid if j in group slice? no:
        // NOTE: hs holds h for THIS group's b-range, all 512 j. Row = bl, col = j.
        float hnew = (1.f - z) * n + z * hold;

        out[((size_t)t * H_ + j) * B_ + b] = hnew;

        // prefetch next-step gates (independent of h)
        if (t + 1 < T_) {
            const float* gq = gp + (size_t)(t + 1) * tstride;
            xr = __ldcs(gq);
            xz = __ldcs(gq + goff);
            xn = __ldcs(gq + 2 * goff);
        }

        // ---- per-group barrier ----
        __syncthreads();
        if (tid == 0) {
            __threadfence();
            unsigned g = g_gen2[gidx];
            if (atomicAdd((unsigned*)&g_cnt[gidx], 1u) == 31u) {
                g_cnt[gidx] = 0u;
                __threadfence();
                g_gen2[gidx] = g + 1u;
            } else {
                while (g_gen2[gidx] == g) { }
            }
            __threadfence();
        }
        __syncthreads();

        // ---- reload group's h slice: hs[b_local][k] <- out[t][k][bg0+b] ----
        {
            const float* src = out + (size_t)t * H_ * B_;
            int kk0 = tid >> 2;          // 0..63
            int q   = tid & 3;           // b-quad
#pragma unroll
            for (int u = 0; u < 8; u++) {
                int k = kk0 + u * 64;
                float4 v = __ldcg(reinterpret_cast<const float4*>(src + (size_t)k * B_ + bg0) + q);
                int bb = q * 4;
                hs[(bb + 0) * HS_STRIDE + k] = v.x;
                hs[(bb + 1) * HS_STRIDE + k] = v.y;
                hs[(bb + 2) * HS_STRIDE + k] = v.z;
                hs[(bb + 3) * HS_STRIDE + k] = v.w;
            }
        }
        __syncthreads();
    }
}

// =========================================================================
// hidden[l][b][h] = out_l[T-1][h][b]
// =========================================================================
__global__ __launch_bounds__(256) void k_hidden(float* __restrict__ dst) {
    int idx = blockIdx.x * 256 + threadIdx.x;
    int l  = idx >> 15;
    int rem = idx & 32767;
    int bb = rem >> 9;
    int h  = rem & 511;
    const float* src = l ? g_out1 : g_out0;
    dst[idx] = src[((size_t)(T_ - 1) * H_ + h) * B_ + bb];
}

// =========================================================================
extern "C" void kernel_launch(void* const* d_in, const int* in_sizes, int n_in,
                              void* d_out, int out_size) {
    const float* x    = (const float*)d_in[0];
    const float* Wih0 = (const float*)d_in[1];
    const float* Whh0 = (const float*)d_in[2];
    const float* bih0 = (const float*)d_in[3];
    const float* bhh0 = (const float*)d_in[4];
    const float* Wih1 = (const float*)d_in[5];
    const float* Whh1 = (const float*)d_in[6];
    const float* bih1 = (const float*)d_in[7];
    const float* bhh1 = (const float*)d_in[8];
    const float* fcw  = (const float*)d_in[9];
    const float* fcb  = (const float*)d_in[10];
    float* out = (float*)d_out;

    (void)in_sizes; (void)n_in; (void)out_size;

    cudaFuncSetAttribute(k_gru2, cudaFuncAttributeMaxDynamicSharedMemorySize,
                         GRU_SMEM_BYTES);

    float *p_xt, *p_gates, *p_out0, *p_out1;
    cudaGetSymbolAddress((void**)&p_xt,    g_xt);
    cudaGetSymbolAddress((void**)&p_gates, g_gates);
    cudaGetSymbolAddress((void**)&p_out0,  g_out0);
    cudaGetSymbolAddress((void**)&p_out1,  g_out1);

    // 1) x -> xt[t][k][b]
    k_transpose<<<dim3(1024, 4), 256>>>(x);
    // 2) gates0 = W_ih0 @ x_t + b_ih0 -> [t][g][b]
    k_gemm2<<<dim3(G_ / 128, T_ / 2), 256>>>(Wih0, p_xt, bih0, p_gates, G_, I_, 0);
    // 3) layer-0 recurrence
    k_gru2<<<128, 256, GRU_SMEM_BYTES>>>(p_gates, Whh0, bhh0, p_out0);
    // 4) gates1 = W_ih1 @ out0_t + b_ih1
    k_gemm2<<<dim3(G_ / 128, T_ / 2), 256>>>(Wih1, p_out0, bih1, p_gates, G_, H_, 0);
    // 5) layer-1 recurrence
    k_gru2<<<128, 256, GRU_SMEM_BYTES>>>(p_gates, Whh1, bhh1, p_out1);
    // 6) FC
    k_gemm2<<<dim3(O_ / 128, T_ / 2), 256>>>(fcw, p_out1, fcb, out, O_, H_, 1);
    // 7) hidden
    k_hidden<<<256, 256>>>(out + (size_t)B_ * T_ * O_);
}

// round 3
// speedup vs baseline: 1.2671x; 1.0875x over previous
#include <cuda_runtime.h>
#include <cstdint>

#define B_ 64
#define T_ 1024
#define I_ 256
#define H_ 512
#define O_ 256
#define G_ 1536   // 3*H

// -------- scratch (device globals: allocation-free) --------
__device__ float g_xt[(size_t)T_ * I_ * B_];      // [t][k][b]
__device__ float g_gates[(size_t)T_ * G_ * B_];   // [t][g][b]
__device__ float g_out0[(size_t)T_ * H_ * B_];    // [t][h][b]
__device__ float g_out1[(size_t)T_ * H_ * B_];    // [t][h][b]
__device__ unsigned g_cnt[4 * 32];                 // per-group barrier counters (padded)
__device__ unsigned g_gen2[4 * 32];                // per-group generations (padded)

// ---------------- async-copy / acquire-release helpers ----------------
__device__ __forceinline__ void cp_async16(void* smem_dst, const void* gsrc) {
    unsigned s = (unsigned)__cvta_generic_to_shared(smem_dst);
    asm volatile("cp.async.ca.shared.global [%0], [%1], 16;" :: "r"(s), "l"(gsrc));
}
__device__ __forceinline__ void cp_commit() {
    asm volatile("cp.async.commit_group;");
}
template <int N>
__device__ __forceinline__ void cp_wait() {
    asm volatile("cp.async.wait_group %0;" :: "n"(N));
}
__device__ __forceinline__ unsigned atom_add_release(unsigned* p, unsigned v) {
    unsigned old;
    asm volatile("atom.add.release.gpu.global.u32 %0, [%1], %2;"
                 : "=r"(old) : "l"(p), "r"(v) : "memory");
    return old;
}
__device__ __forceinline__ unsigned ld_acquire(const unsigned* p) {
    unsigned v;
    asm volatile("ld.acquire.gpu.global.u32 %0, [%1];" : "=r"(v) : "l"(p) : "memory");
    return v;
}
__device__ __forceinline__ void st_release(unsigned* p, unsigned v) {
    asm volatile("st.release.gpu.global.u32 [%0], %1;" :: "l"(p), "r"(v) : "memory");
}

// =========================================================================
// Transpose x[b][t][k] -> xt[t][k][b]
// =========================================================================
__global__ __launch_bounds__(256) void k_transpose(const float* __restrict__ x) {
    __shared__ float sm[64][65];
    int t  = blockIdx.x;
    int k0 = blockIdx.y * 64;
    int c = threadIdx.x & 63;
    int r = threadIdx.x >> 6;
#pragma unroll
    for (int i = 0; i < 16; i++) {
        int b = r + i * 4;
        sm[b][c] = x[((size_t)b * T_ + t) * I_ + k0 + c];
    }
    __syncthreads();
#pragma unroll
    for (int i = 0; i < 16; i++) {
        int kk = r + i * 4;
        g_xt[((size_t)t * I_ + k0 + kk) * B_ + c] = sm[c][kk];
    }
}

// =========================================================================
// cp.async double-buffered GEMM over pairs of timesteps:
//   C_t[M][64] = A[M][K] @ Bt[t][K][64] + bias[M], N-tile = 128 = 2 timesteps
//   mode 0: C[t][m][b]   mode 1: C[(b*T + t)*M + m]
// Tile: 128(M) x 128(N) x 16(K). 256 threads, 8x8 micro-tile.
// As stored [m][k] (stride 20), A-frag reads are warp-broadcast LDS.32.
// =========================================================================
#define AS_STRIDE 20
#define BS_STRIDE 132

__global__ __launch_bounds__(256) void k_gemm3(
    const float* __restrict__ A, const float* __restrict__ Bt,
    const float* __restrict__ bias, float* __restrict__ C,
    int M, int K, int mode)
{
    __shared__ __align__(16) float As[2][128 * AS_STRIDE];
    __shared__ __align__(16) float Bs[2][16 * BS_STRIDE];

    int t0  = blockIdx.y * 2;
    int m0  = blockIdx.x * 128;
    int tid = threadIdx.x;
    int tx  = tid & 15;    // n-sub = tx*8
    int ty  = tid >> 4;    // m-sub = ty*8

    // precompute per-thread load indices
    int a_m0 = tid >> 2;          // chunk 0: m
    int a_q0 = tid & 3;
    int a_m1 = (tid + 256) >> 2;  // chunk 1
    int a_q1 = tid & 3;           // (tid+256)&3 == tid&3

    float acc[8][8];
#pragma unroll
    for (int i = 0; i < 8; i++)
#pragma unroll
        for (int j = 0; j < 8; j++) acc[i][j] = 0.f;

    const float* Bbase = Bt + (size_t)t0 * K * B_;
    int nt = K >> 4;   // number of 16-k tiles

    // ---- issue tile 0 ----
    {
        int k0 = 0;
        cp_async16(&As[0][a_m0 * AS_STRIDE + a_q0 * 4], A + (size_t)(m0 + a_m0) * K + k0 + a_q0 * 4);
        cp_async16(&As[0][a_m1 * AS_STRIDE + a_q1 * 4], A + (size_t)(m0 + a_m1) * K + k0 + a_q1 * 4);
#pragma unroll
        for (int l = 0; l < 2; l++) {
            int f  = tid + l * 256;
            int k  = f >> 5;
            int n4 = f & 31;
            int t2 = n4 >> 4;
            cp_async16(&Bs[0][k * BS_STRIDE + n4 * 4],
                       Bbase + ((size_t)t2 * K + k0 + k) * B_ + (n4 & 15) * 4);
        }
        cp_commit();
    }

    for (int kt = 0; kt < nt; kt++) {
        int cur = kt & 1;
        if (kt + 1 < nt) {
            int nxt = cur ^ 1;
            int k0  = (kt + 1) << 4;
            cp_async16(&As[nxt][a_m0 * AS_STRIDE + a_q0 * 4], A + (size_t)(m0 + a_m0) * K + k0 + a_q0 * 4);
            cp_async16(&As[nxt][a_m1 * AS_STRIDE + a_q1 * 4], A + (size_t)(m0 + a_m1) * K + k0 + a_q1 * 4);
#pragma unroll
            for (int l = 0; l < 2; l++) {
                int f  = tid + l * 256;
                int k  = f >> 5;
                int n4 = f & 31;
                int t2 = n4 >> 4;
                cp_async16(&Bs[nxt][k * BS_STRIDE + n4 * 4],
                           Bbase + ((size_t)t2 * K + k0 + k) * B_ + (n4 & 15) * 4);
            }
            cp_commit();
            cp_wait<1>();
        } else {
            cp_wait<0>();
        }
        __syncthreads();

        const float* Ac = As[cur] + ty * 8 * AS_STRIDE;
        const float* Bc = Bs[cur] + tx * 8;
#pragma unroll
        for (int k = 0; k < 16; k++) {
            float a[8], bv[8];
#pragma unroll
            for (int i = 0; i < 8; i++) a[i] = Ac[i * AS_STRIDE + k];
            *(float4*)&bv[0] = *(const float4*)&Bc[k * BS_STRIDE];
            *(float4*)&bv[4] = *(const float4*)&Bc[k * BS_STRIDE + 4];
#pragma unroll
            for (int i = 0; i < 8; i++)
#pragma unroll
                for (int j = 0; j < 8; j++)
                    acc[i][j] += a[i] * bv[j];
        }
        __syncthreads();
    }

#pragma unroll
    for (int i = 0; i < 8; i++) {
        int m = m0 + ty * 8 + i;
        float bb = bias[m];
#pragma unroll
        for (int j = 0; j < 8; j++) {
            int n = tx * 8 + j;
            int t = t0 + (n >> 6);
            int b = n & 63;
            float v = acc[i][j] + bb;
            if (mode == 0)
                C[((size_t)t * M + m) * B_ + b] = v;
            else
                C[((size_t)b * T_ + t) * M + m] = v;
        }
    }
}

// =========================================================================
// Persistent GRU layer, batch-partitioned groups.
// 128 CTAs = 4 batch-groups (16 b each) x 32 j-subs (16 j each).
// SMEM: Ws slice 48x520 fp32 + h slice [16 b][516].
// Per step: dot from SMEM, gate math, STG h_new, per-group release/acquire
// barrier, reload group's h slice (32KB) from L2, repeat.
// =========================================================================
#define WS_STRIDE 520
#define HS_STRIDE 516
#define GRU_SMEM_FLOATS (48 * WS_STRIDE + 16 * HS_STRIDE)
#define GRU_SMEM_BYTES (GRU_SMEM_FLOATS * 4)

__global__ __launch_bounds__(256) void k_gru3(
    const float* __restrict__ gates,   // [t][g][b], includes b_ih
    const float* __restrict__ Whh,     // [3H][H]
    const float* __restrict__ bhh,     // [3H]
    float* __restrict__ out)           // [t][h][b]
{
    extern __shared__ float smem[];
    float* Ws = smem;                      // 48 rows (jj*3+g) x WS_STRIDE
    float* hs = smem + 48 * WS_STRIDE;     // [16 b][HS_STRIDE]

    int tid   = threadIdx.x;
    int group = blockIdx.x >> 5;    // 0..3 (batch group)
    int sub   = blockIdx.x & 31;    // 0..31 (j partition)
    int jj    = tid >> 4;           // 0..15
    int bl    = tid & 15;           // 0..15
    int j0    = sub * 16;
    int bg0   = group * 16;
    int j     = j0 + jj;
    int b     = bg0 + bl;
    int gidx  = group * 32;

    // Load Whh slice: rows (ww*3+g) <- Whh[g*H + j0 + ww]
    for (int idx = tid; idx < 48 * 512; idx += 256) {
        int r = idx >> 9;
        int k = idx & 511;
        int gg = r % 3;
        int ww = r / 3;
        Ws[r * WS_STRIDE + k] = Whh[((size_t)(gg * H_ + j0 + ww)) * H_ + k];
    }
    for (int idx = tid; idx < 16 * HS_STRIDE; idx += 256) hs[idx] = 0.f;

    float bhr = bhh[j];
    float bhz = bhh[H_ + j];
    float bhn = bhh[2 * H_ + j];

    const float4* Wr = (const float4*)(Ws + (jj * 3 + 0) * WS_STRIDE);
    const float4* Wz = (const float4*)(Ws + (jj * 3 + 1) * WS_STRIDE);
    const float4* Wn = (const float4*)(Ws + (jj * 3 + 2) * WS_STRIDE);
    const float4* hp = (const float4*)(hs + bl * HS_STRIDE);

    const float* gp = gates + (size_t)j * B_ + b;   // gate 0, t=0
    const size_t tstride = (size_t)G_ * B_;
    const size_t goff    = (size_t)H_ * B_;

    // prefetch gates for t=0
    float xr = __ldcs(gp);
    float xz = __ldcs(gp + goff);
    float xn = __ldcs(gp + 2 * goff);

    __syncthreads();

    for (int t = 0; t < T_; t++) {
        float ar = 0.f, az = 0.f, an = 0.f;
#pragma unroll 8
        for (int k4 = 0; k4 < 128; k4++) {
            float4 h4 = hp[k4];
            float4 wr = Wr[k4];
            float4 wz = Wz[k4];
            float4 wn = Wn[k4];
            ar += wr.x * h4.x; az += wz.x * h4.x; an += wn.x * h4.x;
            ar += wr.y * h4.y; az += wz.y * h4.y; an += wn.y * h4.y;
            ar += wr.z * h4.z; az += wz.z * h4.z; an += wn.z * h4.z;
            ar += wr.w * h4.w; az += wz.w * h4.w; an += wn.w * h4.w;
        }

        float r = 1.f / (1.f + expf(-(xr + ar + bhr)));
        float z = 1.f / (1.f + expf(-(xz + az + bhz)));
        float n = tanhf(xn + r * (an + bhn));
        float hold = hs[bl * HS_STRIDE + j];
        float hnew = (1.f - z) * n + z * hold;

        out[((size_t)t * H_ + j) * B_ + b] = hnew;

        // prefetch next-step gates (independent of h)
        if (t + 1 < T_) {
            const float* gq = gp + (size_t)(t + 1) * tstride;
            xr = __ldcs(gq);
            xz = __ldcs(gq + goff);
            xn = __ldcs(gq + 2 * goff);
        }

        // ---- per-group release/acquire barrier ----
        __syncthreads();
        if (tid == 0) {
            unsigned g = g_gen2[gidx];
            if (atom_add_release(&g_cnt[gidx], 1u) == 31u) {
                g_cnt[gidx] = 0u;
                st_release(&g_gen2[gidx], g + 1u);
            } else {
                while (ld_acquire(&g_gen2[gidx]) == g) { }
            }
        }
        __syncthreads();

        // ---- reload group's h slice: hs[b_local][k] <- out[t][k][bg0+b] ----
        {
            const float* src = out + (size_t)t * H_ * B_;
            int kk0 = tid >> 2;          // 0..63
            int q   = tid & 3;           // b-quad
#pragma unroll
            for (int u = 0; u < 8; u++) {
                int k = kk0 + u * 64;
                float4 v = __ldcg(reinterpret_cast<const float4*>(src + (size_t)k * B_ + bg0) + q);
                int bb = q * 4;
                hs[(bb + 0) * HS_STRIDE + k] = v.x;
                hs[(bb + 1) * HS_STRIDE + k] = v.y;
                hs[(bb + 2) * HS_STRIDE + k] = v.z;
                hs[(bb + 3) * HS_STRIDE + k] = v.w;
            }
        }
        __syncthreads();
    }
}

// =========================================================================
// hidden[l][b][h] = out_l[T-1][h][b]
// =========================================================================
__global__ __launch_bounds__(256) void k_hidden(float* __restrict__ dst) {
    int idx = blockIdx.x * 256 + threadIdx.x;
    int l  = idx >> 15;
    int rem = idx & 32767;
    int bb = rem >> 9;
    int h  = rem & 511;
    const float* src = l ? g_out1 : g_out0;
    dst[idx] = src[((size_t)(T_ - 1) * H_ + h) * B_ + bb];
}

// =========================================================================
extern "C" void kernel_launch(void* const* d_in, const int* in_sizes, int n_in,
                              void* d_out, int out_size) {
    const float* x    = (const float*)d_in[0];
    const float* Wih0 = (const float*)d_in[1];
    const float* Whh0 = (const float*)d_in[2];
    const float* bih0 = (const float*)d_in[3];
    const float* bhh0 = (const float*)d_in[4];
    const float* Wih1 = (const float*)d_in[5];
    const float* Whh1 = (const float*)d_in[6];
    const float* bih1 = (const float*)d_in[7];
    const float* bhh1 = (const float*)d_in[8];
    const float* fcw  = (const float*)d_in[9];
    const float* fcb  = (const float*)d_in[10];
    float* out = (float*)d_out;

    (void)in_sizes; (void)n_in; (void)out_size;

    cudaFuncSetAttribute(k_gru3, cudaFuncAttributeMaxDynamicSharedMemorySize,
                         GRU_SMEM_BYTES);

    float *p_xt, *p_gates, *p_out0, *p_out1;
    cudaGetSymbolAddress((void**)&p_xt,    g_xt);
    cudaGetSymbolAddress((void**)&p_gates, g_gates);
    cudaGetSymbolAddress((void**)&p_out0,  g_out0);
    cudaGetSymbolAddress((void**)&p_out1,  g_out1);

    // 1) x -> xt[t][k][b]
    k_transpose<<<dim3(1024, 4), 256>>>(x);
    // 2) gates0 = W_ih0 @ x_t + b_ih0 -> [t][g][b]
    k_gemm3<<<dim3(G_ / 128, T_ / 2), 256>>>(Wih0, p_xt, bih0, p_gates, G_, I_, 0);
    // 3) layer-0 recurrence
    k_gru3<<<128, 256, GRU_SMEM_BYTES>>>(p_gates, Whh0, bhh0, p_out0);
    // 4) gates1 = W_ih1 @ out0_t + b_ih1
    k_gemm3<<<dim3(G_ / 128, T_ / 2), 256>>>(Wih1, p_out0, bih1, p_gates, G_, H_, 0);
    // 5) layer-1 recurrence
    k_gru3<<<128, 256, GRU_SMEM_BYTES>>>(p_gates, Whh1, bhh1, p_out1);
    // 6) FC
    k_gemm3<<<dim3(O_ / 128, T_ / 2), 256>>>(fcw, p_out1, fcb, out, O_, H_, 1);
    // 7) hidden
    k_hidden<<<256, 256>>>(out + (size_t)B_ * T_ * O_);
}

// round 4
// speedup vs baseline: 1.2809x; 1.0108x over previous
#include <cuda_runtime.h>
#include <cstdint>

#define B_ 64
#define T_ 1024
#define I_ 256
#define H_ 512
#define O_ 256
#define G_ 1536   // 3*H

struct __align__(16) ull2 { unsigned long long x, y; };

// packed fp32x2 FMA: acc(lo,hi) += a(lo,hi) * b(lo,hi)
#define FMA2(acc, av, bv) \
    asm("fma.rn.f32x2 %0, %1, %2, %0;" : "+l"(acc) : "l"(av), "l"(bv))

// -------- scratch (device globals: allocation-free) --------
__device__ float g_xt[(size_t)T_ * I_ * B_];      // [t][k][b]
__device__ float g_gates[(size_t)T_ * G_ * B_];   // [t][g][b]
__device__ float g_out0[(size_t)T_ * H_ * B_];    // [t][h][b]
__device__ float g_out1[(size_t)T_ * H_ * B_];    // [t][h][b]
__device__ unsigned g_cnt[4 * 32];
__device__ unsigned g_gen2[4 * 32];

// ---------------- helpers ----------------
__device__ __forceinline__ void cp_async16(void* smem_dst, const void* gsrc) {
    unsigned s = (unsigned)__cvta_generic_to_shared(smem_dst);
    asm volatile("cp.async.ca.shared.global [%0], [%1], 16;" :: "r"(s), "l"(gsrc));
}
__device__ __forceinline__ void cp_commit() {
    asm volatile("cp.async.commit_group;");
}
template <int N>
__device__ __forceinline__ void cp_wait() {
    asm volatile("cp.async.wait_group %0;" :: "n"(N));
}
__device__ __forceinline__ unsigned atom_add_release(unsigned* p, unsigned v) {
    unsigned old;
    asm volatile("atom.add.release.gpu.global.u32 %0, [%1], %2;"
                 : "=r"(old) : "l"(p), "r"(v) : "memory");
    return old;
}
__device__ __forceinline__ unsigned ld_acquire(const unsigned* p) {
    unsigned v;
    asm volatile("ld.acquire.gpu.global.u32 %0, [%1];" : "=r"(v) : "l"(p) : "memory");
    return v;
}
__device__ __forceinline__ void st_release(unsigned* p, unsigned v) {
    asm volatile("st.release.gpu.global.u32 [%0], %1;" :: "l"(p), "r"(v) : "memory");
}
__device__ __forceinline__ unsigned long long dup2(float a) {
    unsigned long long r;
    asm("mov.b64 %0, {%1, %1};" : "=l"(r) : "r"(__float_as_uint(a)));
    return r;
}
__device__ __forceinline__ float sum2(unsigned long long v) {
    unsigned lo, hi;
    asm("mov.b64 {%0, %1}, %2;" : "=r"(lo), "=r"(hi) : "l"(v));
    return __uint_as_float(lo) + __uint_as_float(hi);
}

// =========================================================================
// Transpose x[b][t][k] -> xt[t][k][b]
// =========================================================================
__global__ __launch_bounds__(256) void k_transpose(const float* __restrict__ x) {
    __shared__ float sm[64][65];
    int t  = blockIdx.x;
    int k0 = blockIdx.y * 64;
    int c = threadIdx.x & 63;
    int r = threadIdx.x >> 6;
#pragma unroll
    for (int i = 0; i < 16; i++) {
        int b = r + i * 4;
        sm[b][c] = x[((size_t)b * T_ + t) * I_ + k0 + c];
    }
    __syncthreads();
#pragma unroll
    for (int i = 0; i < 16; i++) {
        int kk = r + i * 4;
        g_xt[((size_t)t * I_ + k0 + kk) * B_ + c] = sm[c][kk];
    }
}

// =========================================================================
// cp.async double-buffered GEMM, f32x2 inner product.
//   C_t[M][64] = A[M][K] @ Bt[t][K][64] + bias[M], N-tile = 128 = 2 timesteps
// Tile 128x128x16, 256 threads, 8(M) x 8(N) micro-tile with N packed in pairs.
// =========================================================================
#define AS_STRIDE 20
#define BS_STRIDE 132

__global__ __launch_bounds__(256, 2) void k_gemm4(
    const float* __restrict__ A, const float* __restrict__ Bt,
    const float* __restrict__ bias, float* __restrict__ C,
    int M, int K, int mode)
{
    __shared__ __align__(16) float As[2][128 * AS_STRIDE];
    __shared__ __align__(16) float Bs[2][16 * BS_STRIDE];

    int t0  = blockIdx.y * 2;
    int m0  = blockIdx.x * 128;
    int tid = threadIdx.x;
    int tx  = tid & 15;    // n-sub = tx*8
    int ty  = tid >> 4;    // m-sub = ty*8

    int a_m0 = tid >> 2;
    int a_q  = tid & 3;
    int a_m1 = a_m0 + 64;

    unsigned long long acc2[8][4];
#pragma unroll
    for (int i = 0; i < 8; i++)
#pragma unroll
        for (int j = 0; j < 4; j++) acc2[i][j] = 0ull;

    const float* Bbase = Bt + (size_t)t0 * K * B_;
    int nt = K >> 4;

    // issue tile 0
    {
        cp_async16(&As[0][a_m0 * AS_STRIDE + a_q * 4], A + (size_t)(m0 + a_m0) * K + a_q * 4);
        cp_async16(&As[0][a_m1 * AS_STRIDE + a_q * 4], A + (size_t)(m0 + a_m1) * K + a_q * 4);
#pragma unroll
        for (int l = 0; l < 2; l++) {
            int f  = tid + l * 256;
            int k  = f >> 5;
            int n4 = f & 31;
            int t2 = n4 >> 4;
            cp_async16(&Bs[0][k * BS_STRIDE + n4 * 4],
                       Bbase + ((size_t)t2 * K + k) * B_ + (n4 & 15) * 4);
        }
        cp_commit();
    }

    for (int kt = 0; kt < nt; kt++) {
        int cur = kt & 1;
        if (kt + 1 < nt) {
            int nxt = cur ^ 1;
            int k0  = (kt + 1) << 4;
            cp_async16(&As[nxt][a_m0 * AS_STRIDE + a_q * 4], A + (size_t)(m0 + a_m0) * K + k0 + a_q * 4);
            cp_async16(&As[nxt][a_m1 * AS_STRIDE + a_q * 4], A + (size_t)(m0 + a_m1) * K + k0 + a_q * 4);
#pragma unroll
            for (int l = 0; l < 2; l++) {
                int f  = tid + l * 256;
                int k  = f >> 5;
                int n4 = f & 31;
                int t2 = n4 >> 4;
                cp_async16(&Bs[nxt][k * BS_STRIDE + n4 * 4],
                           Bbase + ((size_t)t2 * K + k0 + k) * B_ + (n4 & 15) * 4);
            }
            cp_commit();
            cp_wait<1>();
        } else {
            cp_wait<0>();
        }
        __syncthreads();

        const float* Ac = As[cur] + ty * 8 * AS_STRIDE;
        const float* Bc = Bs[cur] + tx * 8;
#pragma unroll
        for (int k4 = 0; k4 < 4; k4++) {
            float4 a4[8];
#pragma unroll
            for (int i = 0; i < 8; i++)
                a4[i] = *(const float4*)(Ac + i * AS_STRIDE + k4 * 4);
#pragma unroll
            for (int kk = 0; kk < 4; kk++) {
                int k = k4 * 4 + kk;
                ull2 b01 = *(const ull2*)(Bc + (size_t)k * BS_STRIDE);
                ull2 b23 = *(const ull2*)(Bc + (size_t)k * BS_STRIDE + 4);
#pragma unroll
                for (int i = 0; i < 8; i++) {
                    float av = (kk == 0) ? a4[i].x : (kk == 1) ? a4[i].y
                             : (kk == 2) ? a4[i].z : a4[i].w;
                    unsigned long long a2 = dup2(av);
                    FMA2(acc2[i][0], a2, b01.x);
                    FMA2(acc2[i][1], a2, b01.y);
                    FMA2(acc2[i][2], a2, b23.x);
                    FMA2(acc2[i][3], a2, b23.y);
                }
            }
        }
        __syncthreads();
    }

#pragma unroll
    for (int i = 0; i < 8; i++) {
        int m = m0 + ty * 8 + i;
        float bb = bias[m];
#pragma unroll
        for (int jp = 0; jp < 4; jp++) {
            unsigned lo, hi;
            asm("mov.b64 {%0, %1}, %2;" : "=r"(lo), "=r"(hi) : "l"(acc2[i][jp]));
#pragma unroll
            for (int e = 0; e < 2; e++) {
                int n = tx * 8 + jp * 2 + e;
                int t = t0 + (n >> 6);
                int b = n & 63;
                float v = __uint_as_float(e ? hi : lo) + bb;
                if (mode == 0)
                    C[((size_t)t * M + m) * B_ + b] = v;
                else
                    C[((size_t)b * T_ + t) * M + m] = v;
            }
        }
    }
}

// =========================================================================
// Persistent GRU layer, f32x2 K-pair packed dot products.
// 128 CTAs = 4 batch-groups (16 b) x 32 j-subs (16 j).
// Warp shape: 4 jj x 8 bl  (h-wavefronts halved vs 2x16).
// =========================================================================
#define WS_STRIDE 520
#define HS_STRIDE 516
#define GRU_SMEM_FLOATS (48 * WS_STRIDE + 16 * HS_STRIDE)
#define GRU_SMEM_BYTES (GRU_SMEM_FLOATS * 4)

__global__ __launch_bounds__(256) void k_gru4(
    const float* __restrict__ gates,   // [t][g][b], includes b_ih
    const float* __restrict__ Whh,     // [3H][H]
    const float* __restrict__ bhh,     // [3H]
    float* __restrict__ out)           // [t][h][b]
{
    extern __shared__ float smem[];
    float* Ws = smem;                      // 48 rows (jj*3+g) x WS_STRIDE
    float* hs = smem + 48 * WS_STRIDE;     // [16 b][HS_STRIDE], k-contiguous

    int tid   = threadIdx.x;
    int w     = tid >> 5;
    int lane  = tid & 31;
    int group = blockIdx.x >> 5;
    int sub   = blockIdx.x & 31;
    int jj    = (w >> 1) * 4 + (lane >> 3);   // 0..15
    int bl    = (w & 1) * 8 + (lane & 7);     // 0..15
    int j0    = sub * 16;
    int bg0   = group * 16;
    int j     = j0 + jj;
    int b     = bg0 + bl;
    int gidx  = group * 32;

    for (int idx = tid; idx < 48 * 512; idx += 256) {
        int r = idx >> 9;
        int k = idx & 511;
        int gg = r % 3;
        int ww = r / 3;
        Ws[r * WS_STRIDE + k] = Whh[((size_t)(gg * H_ + j0 + ww)) * H_ + k];
    }
    for (int idx = tid; idx < 16 * HS_STRIDE; idx += 256) hs[idx] = 0.f;

    float bhr = bhh[j];
    float bhz = bhh[H_ + j];
    float bhn = bhh[2 * H_ + j];

    const ull2* Wr2 = (const ull2*)(Ws + (jj * 3 + 0) * WS_STRIDE);
    const ull2* Wz2 = (const ull2*)(Ws + (jj * 3 + 1) * WS_STRIDE);
    const ull2* Wn2 = (const ull2*)(Ws + (jj * 3 + 2) * WS_STRIDE);
    const ull2* hrow = (const ull2*)(hs + bl * HS_STRIDE);

    const float* gp = gates + (size_t)j * B_ + b;
    const size_t tstride = (size_t)G_ * B_;
    const size_t goff    = (size_t)H_ * B_;

    float xr = __ldcs(gp);
    float xz = __ldcs(gp + goff);
    float xn = __ldcs(gp + 2 * goff);

    __syncthreads();

    for (int t = 0; t < T_; t++) {
        unsigned long long ar2 = 0ull, az2 = 0ull, an2 = 0ull;
#pragma unroll 8
        for (int i = 0; i < 128; i++) {      // i covers k = 4i..4i+3
            ull2 h2 = hrow[i];
            ull2 wr = Wr2[i];
            ull2 wz = Wz2[i];
            ull2 wn = Wn2[i];
            FMA2(ar2, wr.x, h2.x); FMA2(ar2, wr.y, h2.y);
            FMA2(az2, wz.x, h2.x); FMA2(az2, wz.y, h2.y);
            FMA2(an2, wn.x, h2.x); FMA2(an2, wn.y, h2.y);
        }
        float ar = sum2(ar2);
        float az = sum2(az2);
        float an = sum2(an2);

        float r = 1.f / (1.f + expf(-(xr + ar + bhr)));
        float z = 1.f / (1.f + expf(-(xz + az + bhz)));
        float n = tanhf(xn + r * (an + bhn));
        float hold = hs[bl * HS_STRIDE + j];
        float hnew = (1.f - z) * n + z * hold;

        out[((size_t)t * H_ + j) * B_ + b] = hnew;

        if (t + 1 < T_) {
            const float* gq = gp + (size_t)(t + 1) * tstride;
            xr = __ldcs(gq);
            xz = __ldcs(gq + goff);
            xn = __ldcs(gq + 2 * goff);
        }

        // ---- per-group release/acquire barrier ----
        __syncthreads();
        if (tid == 0) {
            unsigned g = g_gen2[gidx];
            if (atom_add_release(&g_cnt[gidx], 1u) == 31u) {
                g_cnt[gidx] = 0u;
                st_release(&g_gen2[gidx], g + 1u);
            } else {
                while (ld_acquire(&g_gen2[gidx]) == g) { }
            }
        }
        __syncthreads();

        // ---- reload group's h slice: hs[b_local][k] <- out[t][k][bg0+b] ----
        {
            const float* src = out + (size_t)t * H_ * B_;
            int kk0 = tid >> 2;
            int q   = tid & 3;
#pragma unroll
            for (int u = 0; u < 8; u++) {
                int k = kk0 + u * 64;
                float4 v = __ldcg(reinterpret_cast<const float4*>(src + (size_t)k * B_ + bg0) + q);
                int bb = q * 4;
                hs[(bb + 0) * HS_STRIDE + k] = v.x;
                hs[(bb + 1) * HS_STRIDE + k] = v.y;
                hs[(bb + 2) * HS_STRIDE + k] = v.z;
                hs[(bb + 3) * HS_STRIDE + k] = v.w;
            }
        }
        __syncthreads();
    }
}

// =========================================================================
// hidden[l][b][h] = out_l[T-1][h][b]
// =========================================================================
__global__ __launch_bounds__(256) void k_hidden(float* __restrict__ dst) {
    int idx = blockIdx.x * 256 + threadIdx.x;
    int l  = idx >> 15;
    int rem = idx & 32767;
    int bb = rem >> 9;
    int h  = rem & 511;
    const float* src = l ? g_out1 : g_out0;
    dst[idx] = src[((size_t)(T_ - 1) * H_ + h) * B_ + bb];
}

// =========================================================================
extern "C" void kernel_launch(void* const* d_in, const int* in_sizes, int n_in,
                              void* d_out, int out_size) {
    const float* x    = (const float*)d_in[0];
    const float* Wih0 = (const float*)d_in[1];
    const float* Whh0 = (const float*)d_in[2];
    const float* bih0 = (const float*)d_in[3];
    const float* bhh0 = (const float*)d_in[4];
    const float* Wih1 = (const float*)d_in[5];
    const float* Whh1 = (const float*)d_in[6];
    const float* bih1 = (const float*)d_in[7];
    const float* bhh1 = (const float*)d_in[8];
    const float* fcw  = (const float*)d_in[9];
    const float* fcb  = (const float*)d_in[10];
    float* out = (float*)d_out;

    (void)in_sizes; (void)n_in; (void)out_size;

    cudaFuncSetAttribute(k_gru4, cudaFuncAttributeMaxDynamicSharedMemorySize,
                         GRU_SMEM_BYTES);

    float *p_xt, *p_gates, *p_out0, *p_out1;
    cudaGetSymbolAddress((void**)&p_xt,    g_xt);
    cudaGetSymbolAddress((void**)&p_gates, g_gates);
    cudaGetSymbolAddress((void**)&p_out0,  g_out0);
    cudaGetSymbolAddress((void**)&p_out1,  g_out1);

    k_transpose<<<dim3(1024, 4), 256>>>(x);
    k_gemm4<<<dim3(G_ / 128, T_ / 2), 256>>>(Wih0, p_xt, bih0, p_gates, G_, I_, 0);
    k_gru4<<<128, 256, GRU_SMEM_BYTES>>>(p_gates, Whh0, bhh0, p_out0);
    k_gemm4<<<dim3(G_ / 128, T_ / 2), 256>>>(Wih1, p_out0, bih1, p_gates, G_, H_, 0);
    k_gru4<<<128, 256, GRU_SMEM_BYTES>>>(p_gates, Whh1, bhh1, p_out1);
    k_gemm4<<<dim3(O_ / 128, T_ / 2), 256>>>(fcw, p_out1, fcb, out, O_, H_, 1);
    k_hidden<<<256, 256>>>(out + (size_t)B_ * T_ * O_);
}

// round 6
// speedup vs baseline: 1.4486x; 1.1310x over previous
#include <cuda_runtime.h>
#include <cuda_bf16.h>
#include <cstdint>

#define B_ 64
#define T_ 1024
#define I_ 256
#define H_ 512
#define O_ 256
#define G_ 1536   // 3*H

struct __align__(16) ull2 { unsigned long long x, y; };

#define FMA2(acc, av, bv) \
    asm("fma.rn.f32x2 %0, %1, %2, %0;" : "+l"(acc) : "l"(av), "l"(bv))

// ======================= scratch (device globals) =======================
__device__ float g_gates[(size_t)T_ * G_ * B_];   // [t][g][b]
__device__ float g_out0[(size_t)T_ * H_ * B_];    // [t][h][b]
__device__ float g_out1[(size_t)T_ * H_ * B_];    // [t][h][b]
__device__ unsigned g_cnt[4 * 32];
__device__ unsigned g_gen2[4 * 32];

// pre-swizzled bf16 operand tiles
// W tiles: [mi][s] of 128x64 bf16 (16KB); X tiles: [t][s] of 64x64 bf16 (8KB)
__device__ __nv_bfloat16 g_w0h[12 * 4 * 8192], g_w0l[12 * 4 * 8192];
__device__ __nv_bfloat16 g_w1h[12 * 8 * 8192], g_w1l[12 * 8 * 8192];
__device__ __nv_bfloat16 g_wfh[ 2 * 8 * 8192], g_wfl[ 2 * 8 * 8192];
__device__ __nv_bfloat16 g_x0h[(size_t)T_ * 4 * 4096], g_x0l[(size_t)T_ * 4 * 4096];
__device__ __nv_bfloat16 g_x1h[(size_t)T_ * 8 * 4096], g_x1l[(size_t)T_ * 8 * 4096];

// ======================= small helpers =======================
__device__ __forceinline__ void cp_async16(void* smem_dst, const void* gsrc) {
    unsigned s = (unsigned)__cvta_generic_to_shared(smem_dst);
    asm volatile("cp.async.ca.shared.global [%0], [%1], 16;" :: "r"(s), "l"(gsrc));
}
__device__ __forceinline__ void cp_commit() {
    asm volatile("cp.async.commit_group;");
}
template <int N>
__device__ __forceinline__ void cp_wait() {
    asm volatile("cp.async.wait_group %0;" :: "n"(N));
}
__device__ __forceinline__ unsigned atom_add_release(unsigned* p, unsigned v) {
    unsigned old;
    asm volatile("atom.add.release.gpu.global.u32 %0, [%1], %2;"
                 : "=r"(old) : "l"(p), "r"(v) : "memory");
    return old;
}
__device__ __forceinline__ unsigned ld_acquire(const unsigned* p) {
    unsigned v;
    asm volatile("ld.acquire.gpu.global.u32 %0, [%1];" : "=r"(v) : "l"(p) : "memory");
    return v;
}
__device__ __forceinline__ void st_release(unsigned* p, unsigned v) {
    asm volatile("st.release.gpu.global.u32 [%0], %1;" :: "l"(p), "r"(v) : "memory");
}
__device__ __forceinline__ float sum2(unsigned long long v) {
    unsigned lo, hi;
    asm("mov.b64 {%0, %1}, %2;" : "=r"(lo), "=r"(hi) : "l"(v));
    return __uint_as_float(lo) + __uint_as_float(hi);
}
__device__ __forceinline__ uint32_t smem_u32(const void* p) {
    return (uint32_t)__cvta_generic_to_shared(p);
}
__host__ __device__ __forceinline__ uint32_t swz128(uint32_t o) {
    return o ^ ((o >> 3) & 0x70);
}
__device__ __forceinline__ unsigned short bf16hi_bits(float v, float& rem) {
    __nv_bfloat16 b = __float2bfloat16(v);
    rem = v - __bfloat162float(b);
    return *reinterpret_cast<unsigned short*>(&b);
}
__device__ __forceinline__ unsigned short bf16_bits(float v) {
    __nv_bfloat16 b = __float2bfloat16(v);
    return *reinterpret_cast<unsigned short*>(&b);
}

// ---- mma.sync / ldmatrix (base-target PTX, lowers to HMMA/LDSM) ----
__device__ __forceinline__ void ldsm_x4(unsigned* r, uint32_t addr) {
    asm volatile("ldmatrix.sync.aligned.m8n8.x4.shared.b16 {%0,%1,%2,%3}, [%4];"
        : "=r"(r[0]), "=r"(r[1]), "=r"(r[2]), "=r"(r[3]) : "r"(addr));
}
__device__ __forceinline__ void mma_bf16(float* d, const unsigned* a, const unsigned* b) {
    asm volatile(
        "mma.sync.aligned.m16n8k16.row.col.f32.bf16.bf16.f32 "
        "{%0,%1,%2,%3}, {%4,%5,%6,%7}, {%8,%9}, {%0,%1,%2,%3};"
        : "+f"(d[0]), "+f"(d[1]), "+f"(d[2]), "+f"(d[3])
        : "r"(a[0]), "r"(a[1]), "r"(a[2]), "r"(a[3]), "r"(b[0]), "r"(b[1]));
}

// =========================================================================
// Prep: W [M,K] fp32 -> hi/lo bf16 SW128 tiles [mi][s][128x64]
// =========================================================================
__global__ __launch_bounds__(256) void k_prep_w(
    const float* __restrict__ src, __nv_bfloat16* __restrict__ dh,
    __nv_bfloat16* __restrict__ dl, int K)
{
    int mi = blockIdx.x, s = blockIdx.y, nS = gridDim.y;
    size_t tbase = ((size_t)mi * nS + s) * 16384;   // bytes
#pragma unroll
    for (int i = 0; i < 8; i++) {
        int it  = threadIdx.x + i * 256;   // 0..2047
        int row = it >> 4;
        int q   = it & 15;
        float4 v = *(const float4*)(src + (size_t)(mi * 128 + row) * K + s * 64 + q * 4);
        float r0, r1, r2, r3;
        ushort4 hi, lo;
        hi.x = bf16hi_bits(v.x, r0); hi.y = bf16hi_bits(v.y, r1);
        hi.z = bf16hi_bits(v.z, r2); hi.w = bf16hi_bits(v.w, r3);
        lo.x = bf16_bits(r0); lo.y = bf16_bits(r1);
        lo.z = bf16_bits(r2); lo.w = bf16_bits(r3);
        uint32_t sw = swz128((uint32_t)(row * 128 + q * 8));
        *(ushort4*)((char*)dh + tbase + sw) = hi;
        *(ushort4*)((char*)dl + tbase + sw) = lo;
    }
}

// =========================================================================
// Prep: x[b][t][k] fp32 -> hi/lo bf16 SW128 tiles [t][s][64(b)x64(k)]
// =========================================================================
__global__ __launch_bounds__(256) void k_prep_x(const float* __restrict__ x) {
    int t = blockIdx.x, s = blockIdx.y, nS = gridDim.y;
    size_t tbase = ((size_t)t * nS + s) * 8192;   // bytes
#pragma unroll
    for (int i = 0; i < 4; i++) {
        int it = threadIdx.x + i * 256;   // 0..1023
        int b  = it >> 4;
        int q  = it & 15;
        float4 v = *(const float4*)(x + ((size_t)b * T_ + t) * I_ + s * 64 + q * 4);
        float r0, r1, r2, r3;
        ushort4 hi, lo;
        hi.x = bf16hi_bits(v.x, r0); hi.y = bf16hi_bits(v.y, r1);
        hi.z = bf16hi_bits(v.z, r2); hi.w = bf16hi_bits(v.w, r3);
        lo.x = bf16_bits(r0); lo.y = bf16_bits(r1);
        lo.z = bf16_bits(r2); lo.w = bf16_bits(r3);
        uint32_t sw = swz128((uint32_t)(b * 128 + q * 8));
        *(ushort4*)((char*)g_x0h + tbase + sw) = hi;
        *(ushort4*)((char*)g_x0l + tbase + sw) = lo;
    }
}

// =========================================================================
// Prep: out[t][h][b] fp32 -> hi/lo bf16 SW128 tiles [t][s][64(b)x64(k)]
// =========================================================================
__global__ __launch_bounds__(256) void k_prep_h(
    const float* __restrict__ src, __nv_bfloat16* __restrict__ dh,
    __nv_bfloat16* __restrict__ dl)
{
    __shared__ float sm[64 * 65];
    int t = blockIdx.x, s = blockIdx.y, nS = gridDim.y;
    size_t tbase = ((size_t)t * nS + s) * 8192;
    const float* blk = src + ((size_t)t * H_ + s * 64) * B_;   // [k][b] 64x64
#pragma unroll
    for (int i = 0; i < 16; i++) {
        int idx = threadIdx.x + i * 256;
        int k = idx >> 6, b = idx & 63;
        sm[k * 65 + b] = blk[idx];
    }
    __syncthreads();
#pragma unroll
    for (int i = 0; i < 4; i++) {
        int it = threadIdx.x + i * 256;
        int b  = it >> 4;
        int q  = it & 15;
        float v0 = sm[(q * 4 + 0) * 65 + b];
        float v1 = sm[(q * 4 + 1) * 65 + b];
        float v2 = sm[(q * 4 + 2) * 65 + b];
        float v3 = sm[(q * 4 + 3) * 65 + b];
        float r0, r1, r2, r3;
        ushort4 hi, lo;
        hi.x = bf16hi_bits(v0, r0); hi.y = bf16hi_bits(v1, r1);
        hi.z = bf16hi_bits(v2, r2); hi.w = bf16hi_bits(v3, r3);
        lo.x = bf16_bits(r0); lo.y = bf16_bits(r1);
        lo.z = bf16_bits(r2); lo.w = bf16_bits(r3);
        uint32_t sw = swz128((uint32_t)(b * 128 + q * 8));
        *(ushort4*)((char*)dh + tbase + sw) = hi;
        *(ushort4*)((char*)dl + tbase + sw) = lo;
    }
}

// =========================================================================
// mma.sync GEMM: C_t[M][64] = W[M,K] @ X_t[K,64] + bias, two t per CTA.
// bf16x3 split: D = Ah*Bh + Ah*Bl + Al*Bh, fp32 register accum.
// Tile 128(M) x 128(N) x 64-k slabs, cp.async double-buffered.
// 8 warps: 4(M) x 2(N); warp = 32M x 64N; m16n8k16 fragments via ldmatrix.
//   mode 0: C[t][m][b]   mode 1: C[(b*T+t)*M + m]
// =========================================================================
#define TCB_BYTES 65536
#define TC_SMEM_TOTAL (1024 + 2 * TCB_BYTES)

__global__ __launch_bounds__(256) void k_gemm_mma(
    const __nv_bfloat16* __restrict__ Wh, const __nv_bfloat16* __restrict__ Wl,
    const __nv_bfloat16* __restrict__ Xh, const __nv_bfloat16* __restrict__ Xl,
    const float* __restrict__ bias, float* __restrict__ C,
    int nS, int M, int mode)
{
    extern __shared__ __align__(16) char smem[];
    uint32_t sb = smem_u32(smem);
    int tid  = threadIdx.x;
    int wid  = tid >> 5;
    int lane = tid & 31;
    int mi   = blockIdx.x;
    int m0   = mi * 128;
    int t0   = blockIdx.y * 2;

    int wm = (wid >> 1) * 32;        // warp m-base (0,32,64,96)
    int wn = (wid & 1);              // warp n-half = timestep select

    // per-thread ldmatrix address patterns (byte offsets within a tile)
    uint32_t pA = (uint32_t)((wm + (lane & 15)) * 128 + (lane >> 4) * 16);
    uint32_t rowB = (uint32_t)((lane & 7) + ((lane >> 4) & 1) * 8);
    uint32_t koffB = (uint32_t)(((lane >> 3) & 1) * 16);

    float acc[2][8][4];
#pragma unroll
    for (int i = 0; i < 2; i++)
#pragma unroll
        for (int n = 0; n < 8; n++)
#pragma unroll
            for (int c = 0; c < 4; c++) acc[i][n][c] = 0.f;

    auto issue_slab = [&](int s, int bi) {
        char* dst = smem + 1024 + bi * TCB_BYTES;
        const char* wh  = (const char*)Wh + ((size_t)mi * nS + s) * 16384;
        const char* wl  = (const char*)Wl + ((size_t)mi * nS + s) * 16384;
        const char* x0h = (const char*)Xh + ((size_t)t0 * nS + s) * 8192;
        const char* x1h = (const char*)Xh + ((size_t)(t0 + 1) * nS + s) * 8192;
        const char* x0l = (const char*)Xl + ((size_t)t0 * nS + s) * 8192;
        const char* x1l = (const char*)Xl + ((size_t)(t0 + 1) * nS + s) * 8192;
#pragma unroll
        for (int i = 0; i < 16; i++) {
            int c   = tid + i * 256;        // 0..4095 16B chunks
            int reg = c >> 10;              // 0 Ah, 1 Al, 2 Bh, 3 Bl
            int off = (c & 1023) * 16;
            const char* src;
            if      (reg == 0) src = wh + off;
            else if (reg == 1) src = wl + off;
            else if (reg == 2) src = (off < 8192) ? x0h + off : x1h + (off - 8192);
            else               src = (off < 8192) ? x0l + off : x1l + (off - 8192);
            cp_async16(dst + reg * 16384 + off, src);
        }
        cp_commit();
    };

    issue_slab(0, 0);

    for (int s = 0; s < nS; s++) {
        int bi = s & 1;
        if (s + 1 < nS) {
            issue_slab(s + 1, (s + 1) & 1);
            cp_wait<1>();
        } else {
            cp_wait<0>();
        }
        __syncthreads();

        uint32_t bufb = sb + 1024 + (uint32_t)bi * TCB_BYTES;
        uint32_t aH = bufb;
        uint32_t aL = bufb + 16384;
        uint32_t bH = bufb + 32768 + (uint32_t)wn * 8192;
        uint32_t bL = bufb + 49152 + (uint32_t)wn * 8192;

#pragma unroll
        for (int ks = 0; ks < 4; ks++) {
            unsigned ah[2][4], al[2][4];
            ldsm_x4(ah[0], aH + swz128(pA + ks * 32));
            ldsm_x4(ah[1], aH + swz128(pA + 2048 + ks * 32));
            ldsm_x4(al[0], aL + swz128(pA + ks * 32));
            ldsm_x4(al[1], aL + swz128(pA + 2048 + ks * 32));
#pragma unroll
            for (int half = 0; half < 2; half++) {
                unsigned bh2[2][4], bl2[2][4];
#pragma unroll
                for (int np2 = 0; np2 < 2; np2++) {
                    int np = half * 2 + np2;
                    uint32_t pB = (uint32_t)((np * 16 + rowB) * 128) + koffB;
                    ldsm_x4(bh2[np2], bH + swz128(pB + ks * 32));
                    ldsm_x4(bl2[np2], bL + swz128(pB + ks * 32));
                }
#pragma unroll
                for (int np2 = 0; np2 < 2; np2++) {
#pragma unroll
                    for (int e = 0; e < 2; e++) {
                        int nt = half * 4 + np2 * 2 + e;
                        const unsigned* bfh = &bh2[np2][e * 2];
                        const unsigned* bfl = &bl2[np2][e * 2];
#pragma unroll
                        for (int i = 0; i < 2; i++) {
                            mma_bf16(acc[i][nt], ah[i], bfh);
                            mma_bf16(acc[i][nt], ah[i], bfl);
                            mma_bf16(acc[i][nt], al[i], bfh);
                        }
                    }
                }
            }
        }
        __syncthreads();
    }

    // ---------------- epilogue ----------------
    int qrow = lane >> 2;            // 0..7
    int qcol = (lane & 3) * 2;       // 0,2,4,6

    if (mode == 0) {
        int t = t0 + wn;
#pragma unroll
        for (int i = 0; i < 2; i++) {
            int r0 = wm + i * 16 + qrow;
            int r1 = r0 + 8;
            float bb0 = bias[m0 + r0];
            float bb1 = bias[m0 + r1];
            float* d0 = C + ((size_t)t * M + m0 + r0) * B_;
            float* d1 = C + ((size_t)t * M + m0 + r1) * B_;
#pragma unroll
            for (int nt = 0; nt < 8; nt++) {
                int col = nt * 8 + qcol;
                *(float2*)(d0 + col) = make_float2(acc[i][nt][0] + bb0, acc[i][nt][1] + bb0);
                *(float2*)(d1 + col) = make_float2(acc[i][nt][2] + bb1, acc[i][nt][3] + bb1);
            }
        }
    } else {
        // stage to smem [m 0..127][n 0..127] stride 132, then transposed write
        float* stage = (float*)(smem + 1024);
#pragma unroll
        for (int i = 0; i < 2; i++) {
            int r0 = wm + i * 16 + qrow;
            int r1 = r0 + 8;
            float bb0 = bias[m0 + r0];
            float bb1 = bias[m0 + r1];
#pragma unroll
            for (int nt = 0; nt < 8; nt++) {
                int col = wn * 64 + nt * 8 + qcol;
                stage[r0 * 132 + col]     = acc[i][nt][0] + bb0;
                stage[r0 * 132 + col + 1] = acc[i][nt][1] + bb0;
                stage[r1 * 132 + col]     = acc[i][nt][2] + bb1;
                stage[r1 * 132 + col + 1] = acc[i][nt][3] + bb1;
            }
        }
        __syncthreads();
        int n    = tid >> 1;       // 0..127
        int half = tid & 1;
        int tt   = t0 + (n >> 6);
        int b2   = n & 63;
        float* dst = C + ((size_t)b2 * T_ + tt) * M + m0 + half * 64;
#pragma unroll
        for (int q = 0; q < 16; q++) {
            float4 v = make_float4(stage[(half * 64 + q * 4 + 0) * 132 + n],
                                   stage[(half * 64 + q * 4 + 1) * 132 + n],
                                   stage[(half * 64 + q * 4 + 2) * 132 + n],
                                   stage[(half * 64 + q * 4 + 3) * 132 + n]);
            *(float4*)(dst + q * 4) = v;
        }
    }
}

// =========================================================================
// Persistent GRU layer (proven R4 version: f32x2, batch-group barriers)
// =========================================================================
#define WS_STRIDE 520
#define HS_STRIDE 516
#define GRU_SMEM_BYTES ((48 * WS_STRIDE + 16 * HS_STRIDE) * 4)

__global__ __launch_bounds__(256) void k_gru4(
    const float* __restrict__ gates,   // [t][g][b], includes b_ih
    const float* __restrict__ Whh,     // [3H][H]
    const float* __restrict__ bhh,     // [3H]
    float* __restrict__ out)           // [t][h][b]
{
    extern __shared__ float smemf[];
    float* Ws = smemf;
    float* hs = smemf + 48 * WS_STRIDE;

    int tid   = threadIdx.x;
    int w     = tid >> 5;
    int lane  = tid & 31;
    int group = blockIdx.x >> 5;
    int sub   = blockIdx.x & 31;
    int jj    = (w >> 1) * 4 + (lane >> 3);
    int bl    = (w & 1) * 8 + (lane & 7);
    int j0    = sub * 16;
    int bg0   = group * 16;
    int j     = j0 + jj;
    int b     = bg0 + bl;
    int gidx  = group * 32;

    for (int idx = tid; idx < 48 * 512; idx += 256) {
        int r = idx >> 9;
        int k = idx & 511;
        int gg = r % 3;
        int ww = r / 3;
        Ws[r * WS_STRIDE + k] = Whh[((size_t)(gg * H_ + j0 + ww)) * H_ + k];
    }
    for (int idx = tid; idx < 16 * HS_STRIDE; idx += 256) hs[idx] = 0.f;

    float bhr = bhh[j];
    float bhz = bhh[H_ + j];
    float bhn = bhh[2 * H_ + j];

    const ull2* Wr2 = (const ull2*)(Ws + (jj * 3 + 0) * WS_STRIDE);
    const ull2* Wz2 = (const ull2*)(Ws + (jj * 3 + 1) * WS_STRIDE);
    const ull2* Wn2 = (const ull2*)(Ws + (jj * 3 + 2) * WS_STRIDE);
    const ull2* hrow = (const ull2*)(hs + bl * HS_STRIDE);

    const float* gp = gates + (size_t)j * B_ + b;
    const size_t tstride = (size_t)G_ * B_;
    const size_t goff    = (size_t)H_ * B_;

    float xr = __ldcs(gp);
    float xz = __ldcs(gp + goff);
    float xn = __ldcs(gp + 2 * goff);

    __syncthreads();

    for (int t = 0; t < T_; t++) {
        unsigned long long ar2 = 0ull, az2 = 0ull, an2 = 0ull;
#pragma unroll 8
        for (int i = 0; i < 128; i++) {
            ull2 h2 = hrow[i];
            ull2 wr = Wr2[i];
            ull2 wz = Wz2[i];
            ull2 wn = Wn2[i];
            FMA2(ar2, wr.x, h2.x); FMA2(ar2, wr.y, h2.y);
            FMA2(az2, wz.x, h2.x); FMA2(az2, wz.y, h2.y);
            FMA2(an2, wn.x, h2.x); FMA2(an2, wn.y, h2.y);
        }
        float ar = sum2(ar2);
        float az = sum2(az2);
        float an = sum2(an2);

        float r = 1.f / (1.f + expf(-(xr + ar + bhr)));
        float z = 1.f / (1.f + expf(-(xz + az + bhz)));
        float n = tanhf(xn + r * (an + bhn));
        float hold = hs[bl * HS_STRIDE + j];
        float hnew = (1.f - z) * n + z * hold;

        out[((size_t)t * H_ + j) * B_ + b] = hnew;

        if (t + 1 < T_) {
            const float* gq = gp + (size_t)(t + 1) * tstride;
            xr = __ldcs(gq);
            xz = __ldcs(gq + goff);
            xn = __ldcs(gq + 2 * goff);
        }

        __syncthreads();
        if (tid == 0) {
            unsigned g = g_gen2[gidx];
            if (atom_add_release(&g_cnt[gidx], 1u) == 31u) {
                g_cnt[gidx] = 0u;
                st_release(&g_gen2[gidx], g + 1u);
            } else {
                while (ld_acquire(&g_gen2[gidx]) == g) { }
            }
        }
        __syncthreads();

        {
            const float* src = out + (size_t)t * H_ * B_;
            int kk0 = tid >> 2;
            int q   = tid & 3;
#pragma unroll
            for (int u = 0; u < 8; u++) {
                int k = kk0 + u * 64;
                float4 v = __ldcg(reinterpret_cast<const float4*>(src + (size_t)k * B_ + bg0) + q);
                int bb = q * 4;
                hs[(bb + 0) * HS_STRIDE + k] = v.x;
                hs[(bb + 1) * HS_STRIDE + k] = v.y;
                hs[(bb + 2) * HS_STRIDE + k] = v.z;
                hs[(bb + 3) * HS_STRIDE + k] = v.w;
            }
        }
        __syncthreads();
    }
}

// =========================================================================
// hidden[l][b][h] = out_l[T-1][h][b]
// =========================================================================
__global__ __launch_bounds__(256) void k_hidden(float* __restrict__ dst) {
    int idx = blockIdx.x * 256 + threadIdx.x;
    int l  = idx >> 15;
    int rem = idx & 32767;
    int bb = rem >> 9;
    int h  = rem & 511;
    const float* src = l ? g_out1 : g_out0;
    dst[idx] = src[((size_t)(T_ - 1) * H_ + h) * B_ + bb];
}

// =========================================================================
extern "C" void kernel_launch(void* const* d_in, const int* in_sizes, int n_in,
                              void* d_out, int out_size) {
    const float* x    = (const float*)d_in[0];
    const float* Wih0 = (const float*)d_in[1];
    const float* Whh0 = (const float*)d_in[2];
    const float* bih0 = (const float*)d_in[3];
    const float* bhh0 = (const float*)d_in[4];
    const float* Wih1 = (const float*)d_in[5];
    const float* Whh1 = (const float*)d_in[6];
    const float* bih1 = (const float*)d_in[7];
    const float* bhh1 = (const float*)d_in[8];
    const float* fcw  = (const float*)d_in[9];
    const float* fcb  = (const float*)d_in[10];
    float* out = (float*)d_out;

    (void)in_sizes; (void)n_in; (void)out_size;

    cudaFuncSetAttribute(k_gru4, cudaFuncAttributeMaxDynamicSharedMemorySize,
                         GRU_SMEM_BYTES);
    cudaFuncSetAttribute(k_gemm_mma, cudaFuncAttributeMaxDynamicSharedMemorySize,
                         TC_SMEM_TOTAL);

    float *p_gates, *p_out0, *p_out1;
    cudaGetSymbolAddress((void**)&p_gates, g_gates);
    cudaGetSymbolAddress((void**)&p_out0,  g_out0);
    cudaGetSymbolAddress((void**)&p_out1,  g_out1);
    __nv_bfloat16 *w0h, *w0l, *w1h, *w1l, *wfh, *wfl, *x0h, *x0l, *x1h, *x1l;
    cudaGetSymbolAddress((void**)&w0h, g_w0h);
    cudaGetSymbolAddress((void**)&w0l, g_w0l);
    cudaGetSymbolAddress((void**)&w1h, g_w1h);
    cudaGetSymbolAddress((void**)&w1l, g_w1l);
    cudaGetSymbolAddress((void**)&wfh, g_wfh);
    cudaGetSymbolAddress((void**)&wfl, g_wfl);
    cudaGetSymbolAddress((void**)&x0h, g_x0h);
    cudaGetSymbolAddress((void**)&x0l, g_x0l);
    cudaGetSymbolAddress((void**)&x1h, g_x1h);
    cudaGetSymbolAddress((void**)&x1l, g_x1l);

    // operand prep
    k_prep_w<<<dim3(12, 4), 256>>>(Wih0, w0h, w0l, I_);
    k_prep_w<<<dim3(12, 8), 256>>>(Wih1, w1h, w1l, H_);
    k_prep_w<<<dim3(2, 8),  256>>>(fcw,  wfh, wfl, H_);
    k_prep_x<<<dim3(1024, 4), 256>>>(x);

    // layer 0
    k_gemm_mma<<<dim3(12, 512), 256, TC_SMEM_TOTAL>>>(w0h, w0l, x0h, x0l, bih0, p_gates, 4, G_, 0);
    k_gru4<<<128, 256, GRU_SMEM_BYTES>>>(p_gates, Whh0, bhh0, p_out0);

    // layer 1
    k_prep_h<<<dim3(1024, 8), 256>>>(p_out0, x1h, x1l);
    k_gemm_mma<<<dim3(12, 512), 256, TC_SMEM_TOTAL>>>(w1h, w1l, x1h, x1l, bih1, p_gates, 8, G_, 0);
    k_gru4<<<128, 256, GRU_SMEM_BYTES>>>(p_gates, Whh1, bhh1, p_out1);

    // FC
    k_prep_h<<<dim3(1024, 8), 256>>>(p_out1, x1h, x1l);
    k_gemm_mma<<<dim3(2, 512), 256, TC_SMEM_TOTAL>>>(wfh, wfl, x1h, x1l, fcb, out, 8, O_, 1);

    k_hidden<<<256, 256>>>(out + (size_t)B_ * T_ * O_);
}